// round 4
// baseline (speedup 1.0000x reference)
#include <cuda_runtime.h>
#include <math.h>

#define BATCH 2
#define NPTS 1024
#define HEIGHT 32
#define CAND 224
#define KNN 64
#define NT 8
#define NCTA (BATCH*(NPTS/NT))
#define KNN_CTAS (BATCH*HEIGHT*4)   // 256: 4 CTAs per (b, 32-point block), 8 queries each

__device__ int   g_idx[BATCH*NPTS*KNN];
__device__ float g_Pt[BATCH*NPTS*128];
__device__ float g_Qt[BATCH*NPTS*128];
__device__ float g_R [BATCH*NPTS*128];
__device__ float g_part[NCTA*2*128];
__device__ float g_stat_a[128];
__device__ float g_stat_c[128];
__device__ float g_xcon[BATCH*384*NPTS];

// monotone float -> unsigned key (no NaNs present)
__device__ __forceinline__ unsigned key32(float f) {
    unsigned b = __float_as_uint(f);
    return b ^ ((b & 0x80000000u) ? 0xFFFFFFFFu : 0x80000000u);
}

// ============ fused: KNN (256 CTAs) || gemm P/Q (rest) ============
__global__ __launch_bounds__(256) void fused_layer(const float* __restrict__ x,
                                                   const float* __restrict__ w,
                                                   int C, int Oc, int bstride)
{
    __shared__ union {
        float cs[8 * CAND];                               // knn candidate tile
        struct { float xs[16*64], w1s[16*65], wds[16*65]; } g;  // gemm tiles
    } sm;

    int bx  = blockIdx.x;
    int tid = threadIdx.x;

    if (bx < KNN_CTAS) {
        // ---------------- KNN: warp-per-query ----------------
        int b   = bx >> 7;
        int rem = bx & 127;
        int i   = rem >> 2;          // 32-point block row
        int sub = rem & 3;           // which 8 queries
        const float* xb = x + (size_t)b * bstride;
        int start = (i - 3) * 32;

        int lane = tid & 31;
        int wq   = tid >> 5;         // warp id 0..7
        int q    = sub * 8 + wq;     // query within block row (0..31)

        float acc[7];
#pragma unroll
        for (int u = 0; u < 7; u++) acc[u] = 0.f;

        for (int c0 = 0; c0 < C; c0 += 8) {
            for (int e = tid; e < 8 * CAND; e += 256) {
                int cc = e / CAND, p = e - cc * CAND;
                int j = start + p;
                sm.cs[cc * CAND + p] = (j >= 0 && j < NPTS) ? xb[(c0 + cc) * NPTS + j] : 0.f;
            }
            __syncthreads();
#pragma unroll
            for (int cc = 0; cc < 8; cc++) {
                float qv = sm.cs[cc * CAND + 96 + q];     // query = candidate slot 96+q
#pragma unroll
                for (int u = 0; u < 7; u++) {
                    float d = qv - sm.cs[cc * CAND + lane + 32 * u];
                    acc[u] = fmaf(d, d, acc[u]);
                }
            }
            __syncthreads();
        }

        // keys in registers; invalid candidates -> 0 sentinel
        unsigned long long pv[7];
#pragma unroll
        for (int u = 0; u < 7; u++) {
            int p = lane + 32 * u;
            int j = start + p;
            pv[u] = (j >= 0 && j < NPTS)
                    ? (((unsigned long long)key32(-acc[u]) << 32) | (unsigned)(~p))
                    : 0ull;
        }

        int n = i * 32 + q;
        int pick0 = 0, pick1 = 0;
        for (int k = 0; k < KNN; k++) {
            unsigned long long best = pv[0];
#pragma unroll
            for (int u = 1; u < 7; u++) if (pv[u] > best) best = pv[u];
#pragma unroll
            for (int s = 16; s > 0; s >>= 1) {
                unsigned long long o2 = __shfl_xor_sync(0xffffffffu, best, s);
                if (o2 > best) best = o2;
            }
            unsigned pos = ~(unsigned)best;
            if ((int)(pos & 31) == lane) {
                int slot = pos >> 5;
#pragma unroll
                for (int u = 0; u < 7; u++)
                    if (u == slot) pv[u] = 0ull;
            }
            if (k < 32) { if (lane == k)      pick0 = start + (int)pos; }
            else        { if (lane == k - 32) pick1 = start + (int)pos; }
        }
        g_idx[(b * NPTS + n) * KNN + lane]      = pick0;
        g_idx[(b * NPTS + n) * KNN + 32 + lane] = pick1;
    } else {
        // ------------- P = W1@x, Q = (W2-W1)@x, stored [b][n][o] -------------
        int gid  = bx - KNN_CTAS;
        int zcnt = Oc >> 6;
        int gz   = gid % zcnt;
        int rest = gid / zcnt;
        int gy   = rest & 15;
        int b    = rest >> 4;

        int nt = gy * 64;
        int ot = gz * 64;
        int tx = tid & 15;   // o sub
        int ty = tid >> 4;   // n sub

        float accP[4][4], accQ[4][4];
#pragma unroll
        for (int a = 0; a < 4; a++)
#pragma unroll
            for (int c = 0; c < 4; c++) { accP[a][c] = 0.f; accQ[a][c] = 0.f; }

        const float* xb = x + (size_t)b * bstride;
        int twoC = 2 * C;

        for (int c0 = 0; c0 < C; c0 += 16) {
            for (int e = tid; e < 1024; e += 256) {
                int kc = e >> 6, nn = e & 63;
                sm.g.xs[kc * 64 + nn] = xb[(c0 + kc) * NPTS + nt + nn];
            }
            for (int e = tid; e < 1024; e += 256) {
                int kc = e & 15, o = e >> 4;
                const float* wr = w + (ot + o) * twoC + c0 + kc;
                float w1 = wr[0];
                float w2 = wr[C];
                sm.g.w1s[kc * 65 + o] = w1;
                sm.g.wds[kc * 65 + o] = w2 - w1;
            }
            __syncthreads();
#pragma unroll
            for (int kc = 0; kc < 16; kc++) {
                float a1[4], ad[4], xv[4];
#pragma unroll
                for (int io = 0; io < 4; io++) { a1[io] = sm.g.w1s[kc*65 + tx + 16*io];
                                                 ad[io] = sm.g.wds[kc*65 + tx + 16*io]; }
#pragma unroll
                for (int in = 0; in < 4; in++) xv[in] = sm.g.xs[kc*64 + ty + 16*in];
#pragma unroll
                for (int io = 0; io < 4; io++)
#pragma unroll
                    for (int in = 0; in < 4; in++) {
                        accP[io][in] = fmaf(a1[io], xv[in], accP[io][in]);
                        accQ[io][in] = fmaf(ad[io], xv[in], accQ[io][in]);
                    }
            }
            __syncthreads();
        }
#pragma unroll
        for (int io = 0; io < 4; io++)
#pragma unroll
            for (int in = 0; in < 4; in++) {
                int o = ot + tx + 16*io;
                int nn = nt + ty + 16*in;
                g_Pt[(b*NPTS + nn)*128 + o] = accP[io][in];
                g_Qt[(b*NPTS + nn)*128 + o] = accQ[io][in];
            }
    }
}

// ---- gather: per (n,o): v_k = P[j_k,o] + Q[n,o]; max, sum, sumsq ----
__global__ void gather_kernel()
{
    int b   = blockIdx.x;
    int n0  = blockIdx.y * NT;
    int O   = blockDim.x;
    int o   = threadIdx.x;

    __shared__ int idxs[NT * KNN];
    for (int e = o; e < NT * KNN; e += O)
        idxs[e] = g_idx[(b * NPTS + n0) * KNN + e];
    __syncthreads();

    float s1a = 0.f, s2a = 0.f;
    for (int t = 0; t < NT; t++) {
        int n = n0 + t;
        float qv = g_Qt[(b * NPTS + n) * 128 + o];
        float m = -3e38f, s1 = 0.f, s2 = 0.f;
#pragma unroll 8
        for (int k = 0; k < KNN; k++) {
            float v = g_Pt[(b * NPTS + idxs[t * KNN + k]) * 128 + o] + qv;
            m = fmaxf(m, v);
            s1 += v;
            s2 = fmaf(v, v, s2);
        }
        g_R[(b * NPTS + n) * 128 + o] = m;
        s1a += s1;
        s2a += s2;
    }
    int cta = b * (NPTS / NT) + blockIdx.y;
    g_part[(cta * 2 + 0) * 128 + o] = s1a;
    g_part[(cta * 2 + 1) * 128 + o] = s2a;
}

// --------- per-channel BN coefficients: one CTA per channel ---------
__global__ void stats_kernel(const float* __restrict__ gm, const float* __restrict__ bt)
{
    int o = blockIdx.x;
    int t = threadIdx.x;   // 64 threads
    double s1 = 0.0, s2 = 0.0;
    for (int c = t; c < NCTA; c += 64) {
        s1 += (double)g_part[(c * 2 + 0) * 128 + o];
        s2 += (double)g_part[(c * 2 + 1) * 128 + o];
    }
    __shared__ double sh1[64], sh2[64];
    sh1[t] = s1; sh2[t] = s2;
    __syncthreads();
#pragma unroll
    for (int s = 32; s > 0; s >>= 1) {
        if (t < s) { sh1[t] += sh1[t + s]; sh2[t] += sh2[t + s]; }
        __syncthreads();
    }
    if (t == 0) {
        double cnt = (double)BATCH * NPTS * KNN;
        double mu  = sh1[0] / cnt;
        double var = sh2[0] / cnt - mu * mu;
        float a = gm[o] / (float)sqrt(var + 1e-5);
        g_stat_a[o] = a;
        g_stat_c[o] = bt[o] - (float)mu * a;
    }
}

// ---- affine-BN + leaky-relu + transpose [b][n][o] -> [b][o][n] ----
__global__ void act_transpose_kernel(float* __restrict__ xout)
{
    __shared__ float t[32][33];
    int b  = blockIdx.x;
    int n0 = blockIdx.y * 32;
    int o0 = blockIdx.z * 32;
    int tx = threadIdx.x, ty = threadIdx.y;
    float a = g_stat_a[o0 + tx];
    float c = g_stat_c[o0 + tx];
    for (int r = ty; r < 32; r += 8) {
        float v = g_R[(b * NPTS + n0 + r) * 128 + o0 + tx];
        v = a * v + c;
        v = (v >= 0.f) ? v : 0.2f * v;
        t[r][tx] = v;
    }
    __syncthreads();
    for (int r = ty; r < 32; r += 8)
        xout[b * 384 * NPTS + (o0 + r) * NPTS + n0 + tx] = t[tx][r];
}

// ---------------- final 384x384 GEMM -> d_out ----------------
__global__ __launch_bounds__(256) void gemm_last(const float* __restrict__ w,
                                                 float* __restrict__ out)
{
    int b  = blockIdx.x;
    int nt = blockIdx.y * 64;
    int ot = blockIdx.z * 64;

    __shared__ float xs[16][64];
    __shared__ float ws[16][65];

    int tid = threadIdx.x;
    int tx = tid & 15;  // n sub
    int ty = tid >> 4;  // o sub

    float acc[4][4];
#pragma unroll
    for (int a = 0; a < 4; a++)
#pragma unroll
        for (int c = 0; c < 4; c++) acc[a][c] = 0.f;

    const float* xb = g_xcon + (size_t)b * 384 * NPTS;
    for (int c0 = 0; c0 < 384; c0 += 16) {
        for (int e = tid; e < 1024; e += 256) {
            int kc = e >> 6, n = e & 63;
            xs[kc][n] = xb[(c0 + kc) * NPTS + nt + n];
        }
        for (int e = tid; e < 1024; e += 256) {
            int kc = e & 15, o = e >> 4;
            ws[kc][o] = w[(ot + o) * 384 + c0 + kc];
        }
        __syncthreads();
#pragma unroll
        for (int kc = 0; kc < 16; kc++) {
            float xv[4], wv[4];
#pragma unroll
            for (int in = 0; in < 4; in++) xv[in] = xs[kc][tx + 16*in];
#pragma unroll
            for (int io = 0; io < 4; io++) wv[io] = ws[kc][ty + 16*io];
#pragma unroll
            for (int io = 0; io < 4; io++)
#pragma unroll
                for (int in = 0; in < 4; in++)
                    acc[io][in] = fmaf(wv[io], xv[in], acc[io][in]);
        }
        __syncthreads();
    }
#pragma unroll
    for (int io = 0; io < 4; io++)
#pragma unroll
        for (int in = 0; in < 4; in++)
            out[(b * 384 + ot + ty + 16*io) * NPTS + nt + tx + 16*in] = acc[io][in];
}

extern "C" void kernel_launch(void* const* d_in, const int* in_sizes, int n_in,
                              void* d_out, int out_size)
{
    const float* x  = (const float*)d_in[0];
    const float* w[4]  = {(const float*)d_in[1], (const float*)d_in[4],
                          (const float*)d_in[7], (const float*)d_in[10]};
    const float* gm[4] = {(const float*)d_in[2], (const float*)d_in[5],
                          (const float*)d_in[8], (const float*)d_in[11]};
    const float* bt[4] = {(const float*)d_in[3], (const float*)d_in[6],
                          (const float*)d_in[9], (const float*)d_in[12]};
    const float* wl = (const float*)d_in[13];

    float* xcon = nullptr;
    cudaGetSymbolAddress((void**)&xcon, g_xcon);

    const int Cin[4]     = {256, 128, 128, 64};
    const int Oc[4]      = {128, 128, 64, 64};
    const int coffIn[4]  = {0, 0, 128, 256};
    const int coffOut[4] = {0, 128, 256, 320};

    for (int L = 0; L < 4; L++) {
        const float* xin;
        int bstride;
        if (L == 0) { xin = x;                        bstride = 256 * NPTS; }
        else        { xin = xcon + coffIn[L] * NPTS;  bstride = 384 * NPTS; }

        int gemm_ctas = BATCH * 16 * (Oc[L] / 64);
        fused_layer<<<KNN_CTAS + gemm_ctas, 256>>>(xin, w[L], Cin[L], Oc[L], bstride);
        gather_kernel<<<dim3(BATCH, NPTS / NT), Oc[L]>>>();
        stats_kernel<<<Oc[L], 64>>>(gm[L], bt[L]);
        act_transpose_kernel<<<dim3(BATCH, NPTS / 32, Oc[L] / 32), dim3(32, 8)>>>(
            xcon + coffOut[L] * NPTS);
    }
    gemm_last<<<dim3(BATCH, NPTS / 64, 384 / 64), 256>>>(wl, (float*)d_out);
}

// round 5
// speedup vs baseline: 1.0008x; 1.0008x over previous
#include <cuda_runtime.h>
#include <math.h>

#define BATCH 2
#define NPTS 1024
#define HEIGHT 32
#define CAND 224
#define KNN 64
#define NT 8
#define NCTA (BATCH*(NPTS/NT))
#define KNN_CTAS (BATCH*HEIGHT*4)   // 256: 4 CTAs per (b, 32-point block), 8 queries each

__device__ int   g_idx[BATCH*NPTS*KNN];
__device__ float g_Pt[BATCH*NPTS*128];
__device__ float g_Qt[BATCH*NPTS*128];
__device__ float g_R [BATCH*NPTS*128];
__device__ float g_part[NCTA*2*128];
__device__ float g_stat_a[128];
__device__ float g_stat_c[128];
__device__ float g_xcon[BATCH*384*NPTS];

// monotone float -> unsigned key (no NaNs present)
__device__ __forceinline__ unsigned key32(float f) {
    unsigned b = __float_as_uint(f);
    return b ^ ((b & 0x80000000u) ? 0xFFFFFFFFu : 0x80000000u);
}

// ============ fused: KNN (256 CTAs) || gemm P/Q (rest) ============
__global__ __launch_bounds__(256) void fused_layer(const float* __restrict__ x,
                                                   const float* __restrict__ w,
                                                   int C, int Oc, int bstride)
{
    __shared__ union {
        float cs[8 * CAND];                               // knn candidate tile
        struct { float xs[16*64], w1s[16*65], wds[16*65]; } g;  // gemm tiles
    } sm;

    int bx  = blockIdx.x;
    int tid = threadIdx.x;

    if (bx < KNN_CTAS) {
        // ---------------- KNN: warp-per-query ----------------
        int b   = bx >> 7;
        int rem = bx & 127;
        int i   = rem >> 2;          // 32-point block row
        int sub = rem & 3;           // which 8 queries
        const float* xb = x + (size_t)b * bstride;
        int start = (i - 3) * 32;

        int lane = tid & 31;
        int wq   = tid >> 5;         // warp id 0..7
        int q    = sub * 8 + wq;     // query within block row (0..31)

        float acc[7];
#pragma unroll
        for (int u = 0; u < 7; u++) acc[u] = 0.f;

        for (int c0 = 0; c0 < C; c0 += 8) {
            for (int e = tid; e < 8 * CAND; e += 256) {
                int cc = e / CAND, p = e - cc * CAND;
                int j = start + p;
                sm.cs[cc * CAND + p] = (j >= 0 && j < NPTS) ? xb[(c0 + cc) * NPTS + j] : 0.f;
            }
            __syncthreads();
#pragma unroll
            for (int cc = 0; cc < 8; cc++) {
                float qv = sm.cs[cc * CAND + 96 + q];     // query = candidate slot 96+q
#pragma unroll
                for (int u = 0; u < 7; u++) {
                    float d = qv - sm.cs[cc * CAND + lane + 32 * u];
                    acc[u] = fmaf(d, d, acc[u]);
                }
            }
            __syncthreads();
        }

        // keys in registers; invalid candidates -> 0 sentinel
        unsigned long long pv[7];
#pragma unroll
        for (int u = 0; u < 7; u++) {
            int p = lane + 32 * u;
            int j = start + p;
            pv[u] = (j >= 0 && j < NPTS)
                    ? (((unsigned long long)key32(-acc[u]) << 32) | (unsigned)(~p))
                    : 0ull;
        }

        int n = i * 32 + q;
        int pick0 = 0, pick1 = 0;
        for (int k = 0; k < KNN; k++) {
            unsigned long long best = pv[0];
#pragma unroll
            for (int u = 1; u < 7; u++) if (pv[u] > best) best = pv[u];
#pragma unroll
            for (int s = 16; s > 0; s >>= 1) {
                unsigned long long o2 = __shfl_xor_sync(0xffffffffu, best, s);
                if (o2 > best) best = o2;
            }
            unsigned pos = ~(unsigned)best;
            if ((int)(pos & 31) == lane) {
                int slot = pos >> 5;
#pragma unroll
                for (int u = 0; u < 7; u++)
                    if (u == slot) pv[u] = 0ull;
            }
            if (k < 32) { if (lane == k)      pick0 = start + (int)pos; }
            else        { if (lane == k - 32) pick1 = start + (int)pos; }
        }
        g_idx[(b * NPTS + n) * KNN + lane]      = pick0;
        g_idx[(b * NPTS + n) * KNN + 32 + lane] = pick1;
    } else {
        // ------------- P = W1@x, Q = (W2-W1)@x, stored [b][n][o] -------------
        int gid  = bx - KNN_CTAS;
        int zcnt = Oc >> 6;
        int gz   = gid % zcnt;
        int rest = gid / zcnt;
        int gy   = rest & 15;
        int b    = rest >> 4;

        int nt = gy * 64;
        int ot = gz * 64;
        int tx = tid & 15;   // o sub
        int ty = tid >> 4;   // n sub

        float accP[4][4], accQ[4][4];
#pragma unroll
        for (int a = 0; a < 4; a++)
#pragma unroll
            for (int c = 0; c < 4; c++) { accP[a][c] = 0.f; accQ[a][c] = 0.f; }

        const float* xb = x + (size_t)b * bstride;
        int twoC = 2 * C;

        for (int c0 = 0; c0 < C; c0 += 16) {
            for (int e = tid; e < 1024; e += 256) {
                int kc = e >> 6, nn = e & 63;
                sm.g.xs[kc * 64 + nn] = xb[(c0 + kc) * NPTS + nt + nn];
            }
            for (int e = tid; e < 1024; e += 256) {
                int kc = e & 15, o = e >> 4;
                const float* wr = w + (ot + o) * twoC + c0 + kc;
                float w1 = wr[0];
                float w2 = wr[C];
                sm.g.w1s[kc * 65 + o] = w1;
                sm.g.wds[kc * 65 + o] = w2 - w1;
            }
            __syncthreads();
#pragma unroll
            for (int kc = 0; kc < 16; kc++) {
                float a1[4], ad[4], xv[4];
#pragma unroll
                for (int io = 0; io < 4; io++) { a1[io] = sm.g.w1s[kc*65 + tx + 16*io];
                                                 ad[io] = sm.g.wds[kc*65 + tx + 16*io]; }
#pragma unroll
                for (int in = 0; in < 4; in++) xv[in] = sm.g.xs[kc*64 + ty + 16*in];
#pragma unroll
                for (int io = 0; io < 4; io++)
#pragma unroll
                    for (int in = 0; in < 4; in++) {
                        accP[io][in] = fmaf(a1[io], xv[in], accP[io][in]);
                        accQ[io][in] = fmaf(ad[io], xv[in], accQ[io][in]);
                    }
            }
            __syncthreads();
        }
#pragma unroll
        for (int io = 0; io < 4; io++)
#pragma unroll
            for (int in = 0; in < 4; in++) {
                int o = ot + tx + 16*io;
                int nn = nt + ty + 16*in;
                g_Pt[(b*NPTS + nn)*128 + o] = accP[io][in];
                g_Qt[(b*NPTS + nn)*128 + o] = accQ[io][in];
            }
    }
}

// ---- gather: per (n,o): v_k = P[j_k,o] + Q[n,o]; max, sum, sumsq ----
__global__ void gather_kernel()
{
    int b   = blockIdx.x;
    int n0  = blockIdx.y * NT;
    int O   = blockDim.x;
    int o   = threadIdx.x;

    __shared__ int idxs[NT * KNN];
    for (int e = o; e < NT * KNN; e += O)
        idxs[e] = g_idx[(b * NPTS + n0) * KNN + e];
    __syncthreads();

    float s1a = 0.f, s2a = 0.f;
    for (int t = 0; t < NT; t++) {
        int n = n0 + t;
        float qv = g_Qt[(b * NPTS + n) * 128 + o];
        float m = -3e38f, s1 = 0.f, s2 = 0.f;
#pragma unroll 8
        for (int k = 0; k < KNN; k++) {
            float v = g_Pt[(b * NPTS + idxs[t * KNN + k]) * 128 + o] + qv;
            m = fmaxf(m, v);
            s1 += v;
            s2 = fmaf(v, v, s2);
        }
        g_R[(b * NPTS + n) * 128 + o] = m;
        s1a += s1;
        s2a += s2;
    }
    int cta = b * (NPTS / NT) + blockIdx.y;
    g_part[(cta * 2 + 0) * 128 + o] = s1a;
    g_part[(cta * 2 + 1) * 128 + o] = s2a;
}

// --------- per-channel BN coefficients: one CTA per channel ---------
__global__ void stats_kernel(const float* __restrict__ gm, const float* __restrict__ bt)
{
    int o = blockIdx.x;
    int t = threadIdx.x;   // 64 threads
    double s1 = 0.0, s2 = 0.0;
    for (int c = t; c < NCTA; c += 64) {
        s1 += (double)g_part[(c * 2 + 0) * 128 + o];
        s2 += (double)g_part[(c * 2 + 1) * 128 + o];
    }
    __shared__ double sh1[64], sh2[64];
    sh1[t] = s1; sh2[t] = s2;
    __syncthreads();
#pragma unroll
    for (int s = 32; s > 0; s >>= 1) {
        if (t < s) { sh1[t] += sh1[t + s]; sh2[t] += sh2[t + s]; }
        __syncthreads();
    }
    if (t == 0) {
        double cnt = (double)BATCH * NPTS * KNN;
        double mu  = sh1[0] / cnt;
        double var = sh2[0] / cnt - mu * mu;
        float a = gm[o] / (float)sqrt(var + 1e-5);
        g_stat_a[o] = a;
        g_stat_c[o] = bt[o] - (float)mu * a;
    }
}

// ---- affine-BN + leaky-relu + transpose [b][n][o] -> [b][o][n] ----
__global__ void act_transpose_kernel(float* __restrict__ xout)
{
    __shared__ float t[32][33];
    int b  = blockIdx.x;
    int n0 = blockIdx.y * 32;
    int o0 = blockIdx.z * 32;
    int tx = threadIdx.x, ty = threadIdx.y;
    float a = g_stat_a[o0 + tx];
    float c = g_stat_c[o0 + tx];
    for (int r = ty; r < 32; r += 8) {
        float v = g_R[(b * NPTS + n0 + r) * 128 + o0 + tx];
        v = a * v + c;
        v = (v >= 0.f) ? v : 0.2f * v;
        t[r][tx] = v;
    }
    __syncthreads();
    for (int r = ty; r < 32; r += 8)
        xout[b * 384 * NPTS + (o0 + r) * NPTS + n0 + tx] = t[tx][r];
}

// ---------------- final 384x384 GEMM -> d_out ----------------
__global__ __launch_bounds__(256) void gemm_last(const float* __restrict__ w,
                                                 float* __restrict__ out)
{
    int b  = blockIdx.x;
    int nt = blockIdx.y * 64;
    int ot = blockIdx.z * 64;

    __shared__ float xs[16][64];
    __shared__ float ws[16][65];

    int tid = threadIdx.x;
    int tx = tid & 15;  // n sub
    int ty = tid >> 4;  // o sub

    float acc[4][4];
#pragma unroll
    for (int a = 0; a < 4; a++)
#pragma unroll
        for (int c = 0; c < 4; c++) acc[a][c] = 0.f;

    const float* xb = g_xcon + (size_t)b * 384 * NPTS;
    for (int c0 = 0; c0 < 384; c0 += 16) {
        for (int e = tid; e < 1024; e += 256) {
            int kc = e >> 6, n = e & 63;
            xs[kc][n] = xb[(c0 + kc) * NPTS + nt + n];
        }
        for (int e = tid; e < 1024; e += 256) {
            int kc = e & 15, o = e >> 4;
            ws[kc][o] = w[(ot + o) * 384 + c0 + kc];
        }
        __syncthreads();
#pragma unroll
        for (int kc = 0; kc < 16; kc++) {
            float xv[4], wv[4];
#pragma unroll
            for (int in = 0; in < 4; in++) xv[in] = xs[kc][tx + 16*in];
#pragma unroll
            for (int io = 0; io < 4; io++) wv[io] = ws[kc][ty + 16*io];
#pragma unroll
            for (int io = 0; io < 4; io++)
#pragma unroll
                for (int in = 0; in < 4; in++)
                    acc[io][in] = fmaf(wv[io], xv[in], acc[io][in]);
        }
        __syncthreads();
    }
#pragma unroll
    for (int io = 0; io < 4; io++)
#pragma unroll
        for (int in = 0; in < 4; in++)
            out[(b * 384 + ot + ty + 16*io) * NPTS + nt + tx + 16*in] = acc[io][in];
}

extern "C" void kernel_launch(void* const* d_in, const int* in_sizes, int n_in,
                              void* d_out, int out_size)
{
    const float* x  = (const float*)d_in[0];
    const float* w[4]  = {(const float*)d_in[1], (const float*)d_in[4],
                          (const float*)d_in[7], (const float*)d_in[10]};
    const float* gm[4] = {(const float*)d_in[2], (const float*)d_in[5],
                          (const float*)d_in[8], (const float*)d_in[11]};
    const float* bt[4] = {(const float*)d_in[3], (const float*)d_in[6],
                          (const float*)d_in[9], (const float*)d_in[12]};
    const float* wl = (const float*)d_in[13];

    float* xcon = nullptr;
    cudaGetSymbolAddress((void**)&xcon, g_xcon);

    const int Cin[4]     = {256, 128, 128, 64};
    const int Oc[4]      = {128, 128, 64, 64};
    const int coffIn[4]  = {0, 0, 128, 256};
    const int coffOut[4] = {0, 128, 256, 320};

    for (int L = 0; L < 4; L++) {
        const float* xin;
        int bstride;
        if (L == 0) { xin = x;                        bstride = 256 * NPTS; }
        else        { xin = xcon + coffIn[L] * NPTS;  bstride = 384 * NPTS; }

        int gemm_ctas = BATCH * 16 * (Oc[L] / 64);
        fused_layer<<<KNN_CTAS + gemm_ctas, 256>>>(xin, w[L], Cin[L], Oc[L], bstride);
        gather_kernel<<<dim3(BATCH, NPTS / NT), Oc[L]>>>();
        stats_kernel<<<Oc[L], 64>>>(gm[L], bt[L]);
        act_transpose_kernel<<<dim3(BATCH, NPTS / 32, Oc[L] / 32), dim3(32, 8)>>>(
            xcon + coffOut[L] * NPTS);
    }
    gemm_last<<<dim3(BATCH, NPTS / 64, 384 / 64), 256>>>(wl, (float*)d_out);
}

// round 6
// speedup vs baseline: 1.0017x; 1.0009x over previous
#include <cuda_runtime.h>
#include <math.h>

#define BATCH 2
#define NPTS 1024
#define HEIGHT 32
#define CAND 224
#define KNN 64
#define NT 8
#define NCTA (BATCH*(NPTS/NT))
#define KNN_CTAS (BATCH*HEIGHT*4)   // 256: 4 CTAs per (b, 32-point block), 8 queries each

__device__ int   g_idx[BATCH*NPTS*KNN];
__device__ float g_Pt[BATCH*NPTS*128];
__device__ float g_Qt[BATCH*NPTS*128];
__device__ float g_R [BATCH*NPTS*128];
__device__ float g_part[NCTA*2*128];
__device__ float g_stat_a[128];
__device__ float g_stat_c[128];
__device__ float g_xcon[BATCH*384*NPTS];

// monotone float -> unsigned key (no NaNs present)
__device__ __forceinline__ unsigned key32(float f) {
    unsigned b = __float_as_uint(f);
    return b ^ ((b & 0x80000000u) ? 0xFFFFFFFFu : 0x80000000u);
}

// ============ fused: KNN (256 CTAs) || gemm P/Q (rest) ============
__global__ __launch_bounds__(256) void fused_layer(const float* __restrict__ x,
                                                   const float* __restrict__ w,
                                                   int C, int Oc, int bstride)
{
    __shared__ union {
        float cs[8 * CAND];                               // knn candidate tile
        struct { float xs[16*64], w1s[16*65], wds[16*65]; } g;  // gemm tiles
    } sm;

    int bx  = blockIdx.x;
    int tid = threadIdx.x;

    if (bx < KNN_CTAS) {
        // ---------------- KNN: warp-per-query ----------------
        int b   = bx >> 7;
        int rem = bx & 127;
        int i   = rem >> 2;          // 32-point block row
        int sub = rem & 3;           // which 8 queries
        const float* xb = x + (size_t)b * bstride;
        int start = (i - 3) * 32;

        int lane = tid & 31;
        int wq   = tid >> 5;         // warp id 0..7
        int q    = sub * 8 + wq;     // query within block row (0..31)

        float acc[7];
#pragma unroll
        for (int u = 0; u < 7; u++) acc[u] = 0.f;

        for (int c0 = 0; c0 < C; c0 += 8) {
            for (int e = tid; e < 8 * CAND; e += 256) {
                int cc = e / CAND, p = e - cc * CAND;
                int j = start + p;
                sm.cs[cc * CAND + p] = (j >= 0 && j < NPTS) ? xb[(c0 + cc) * NPTS + j] : 0.f;
            }
            __syncthreads();
#pragma unroll
            for (int cc = 0; cc < 8; cc++) {
                float qv = sm.cs[cc * CAND + 96 + q];     // query = candidate slot 96+q
#pragma unroll
                for (int u = 0; u < 7; u++) {
                    float d = qv - sm.cs[cc * CAND + lane + 32 * u];
                    acc[u] = fmaf(d, d, acc[u]);
                }
            }
            __syncthreads();
        }

        // keys in registers; invalid candidates -> 0 sentinel
        unsigned long long pv[7];
#pragma unroll
        for (int u = 0; u < 7; u++) {
            int p = lane + 32 * u;
            int j = start + p;
            pv[u] = (j >= 0 && j < NPTS)
                    ? (((unsigned long long)key32(-acc[u]) << 32) | (unsigned)(~p))
                    : 0ull;
        }

        int n = i * 32 + q;
        int pick0 = 0, pick1 = 0;
        for (int k = 0; k < KNN; k++) {
            unsigned long long best = pv[0];
#pragma unroll
            for (int u = 1; u < 7; u++) if (pv[u] > best) best = pv[u];
#pragma unroll
            for (int s = 16; s > 0; s >>= 1) {
                unsigned long long o2 = __shfl_xor_sync(0xffffffffu, best, s);
                if (o2 > best) best = o2;
            }
            unsigned pos = ~(unsigned)best;
            if ((int)(pos & 31) == lane) {
                int slot = pos >> 5;
#pragma unroll
                for (int u = 0; u < 7; u++)
                    if (u == slot) pv[u] = 0ull;
            }
            if (k < 32) { if (lane == k)      pick0 = start + (int)pos; }
            else        { if (lane == k - 32) pick1 = start + (int)pos; }
        }
        g_idx[(b * NPTS + n) * KNN + lane]      = pick0;
        g_idx[(b * NPTS + n) * KNN + 32 + lane] = pick1;
    } else {
        // ------------- P = W1@x, Q = (W2-W1)@x, stored [b][n][o] -------------
        int gid  = bx - KNN_CTAS;
        int zcnt = Oc >> 6;
        int gz   = gid % zcnt;
        int rest = gid / zcnt;
        int gy   = rest & 15;
        int b    = rest >> 4;

        int nt = gy * 64;
        int ot = gz * 64;
        int tx = tid & 15;   // o sub
        int ty = tid >> 4;   // n sub

        float accP[4][4], accQ[4][4];
#pragma unroll
        for (int a = 0; a < 4; a++)
#pragma unroll
            for (int c = 0; c < 4; c++) { accP[a][c] = 0.f; accQ[a][c] = 0.f; }

        const float* xb = x + (size_t)b * bstride;
        int twoC = 2 * C;

        for (int c0 = 0; c0 < C; c0 += 16) {
            for (int e = tid; e < 1024; e += 256) {
                int kc = e >> 6, nn = e & 63;
                sm.g.xs[kc * 64 + nn] = xb[(c0 + kc) * NPTS + nt + nn];
            }
            for (int e = tid; e < 1024; e += 256) {
                int kc = e & 15, o = e >> 4;
                const float* wr = w + (ot + o) * twoC + c0 + kc;
                float w1 = wr[0];
                float w2 = wr[C];
                sm.g.w1s[kc * 65 + o] = w1;
                sm.g.wds[kc * 65 + o] = w2 - w1;
            }
            __syncthreads();
#pragma unroll
            for (int kc = 0; kc < 16; kc++) {
                float a1[4], ad[4], xv[4];
#pragma unroll
                for (int io = 0; io < 4; io++) { a1[io] = sm.g.w1s[kc*65 + tx + 16*io];
                                                 ad[io] = sm.g.wds[kc*65 + tx + 16*io]; }
#pragma unroll
                for (int in = 0; in < 4; in++) xv[in] = sm.g.xs[kc*64 + ty + 16*in];
#pragma unroll
                for (int io = 0; io < 4; io++)
#pragma unroll
                    for (int in = 0; in < 4; in++) {
                        accP[io][in] = fmaf(a1[io], xv[in], accP[io][in]);
                        accQ[io][in] = fmaf(ad[io], xv[in], accQ[io][in]);
                    }
            }
            __syncthreads();
        }
#pragma unroll
        for (int io = 0; io < 4; io++)
#pragma unroll
            for (int in = 0; in < 4; in++) {
                int o = ot + tx + 16*io;
                int nn = nt + ty + 16*in;
                g_Pt[(b*NPTS + nn)*128 + o] = accP[io][in];
                g_Qt[(b*NPTS + nn)*128 + o] = accQ[io][in];
            }
    }
}

// ---- gather: per (n,o): v_k = P[j_k,o] + Q[n,o]; max, sum, sumsq ----
__global__ void gather_kernel()
{
    int b   = blockIdx.x;
    int n0  = blockIdx.y * NT;
    int O   = blockDim.x;
    int o   = threadIdx.x;

    __shared__ int idxs[NT * KNN];
    for (int e = o; e < NT * KNN; e += O)
        idxs[e] = g_idx[(b * NPTS + n0) * KNN + e];
    __syncthreads();

    float s1a = 0.f, s2a = 0.f;
    for (int t = 0; t < NT; t++) {
        int n = n0 + t;
        float qv = g_Qt[(b * NPTS + n) * 128 + o];
        float m = -3e38f, s1 = 0.f, s2 = 0.f;
#pragma unroll 8
        for (int k = 0; k < KNN; k++) {
            float v = g_Pt[(b * NPTS + idxs[t * KNN + k]) * 128 + o] + qv;
            m = fmaxf(m, v);
            s1 += v;
            s2 = fmaf(v, v, s2);
        }
        g_R[(b * NPTS + n) * 128 + o] = m;
        s1a += s1;
        s2a += s2;
    }
    int cta = b * (NPTS / NT) + blockIdx.y;
    g_part[(cta * 2 + 0) * 128 + o] = s1a;
    g_part[(cta * 2 + 1) * 128 + o] = s2a;
}

// --------- per-channel BN coefficients: one CTA per channel ---------
__global__ void stats_kernel(const float* __restrict__ gm, const float* __restrict__ bt)
{
    int o = blockIdx.x;
    int t = threadIdx.x;   // 64 threads
    double s1 = 0.0, s2 = 0.0;
    for (int c = t; c < NCTA; c += 64) {
        s1 += (double)g_part[(c * 2 + 0) * 128 + o];
        s2 += (double)g_part[(c * 2 + 1) * 128 + o];
    }
    __shared__ double sh1[64], sh2[64];
    sh1[t] = s1; sh2[t] = s2;
    __syncthreads();
#pragma unroll
    for (int s = 32; s > 0; s >>= 1) {
        if (t < s) { sh1[t] += sh1[t + s]; sh2[t] += sh2[t + s]; }
        __syncthreads();
    }
    if (t == 0) {
        double cnt = (double)BATCH * NPTS * KNN;
        double mu  = sh1[0] / cnt;
        double var = sh2[0] / cnt - mu * mu;
        float a = gm[o] / (float)sqrt(var + 1e-5);
        g_stat_a[o] = a;
        g_stat_c[o] = bt[o] - (float)mu * a;
    }
}

// ---- affine-BN + leaky-relu + transpose [b][n][o] -> [b][o][n] ----
__global__ void act_transpose_kernel(float* __restrict__ xout)
{
    __shared__ float t[32][33];
    int b  = blockIdx.x;
    int n0 = blockIdx.y * 32;
    int o0 = blockIdx.z * 32;
    int tx = threadIdx.x, ty = threadIdx.y;
    float a = g_stat_a[o0 + tx];
    float c = g_stat_c[o0 + tx];
    for (int r = ty; r < 32; r += 8) {
        float v = g_R[(b * NPTS + n0 + r) * 128 + o0 + tx];
        v = a * v + c;
        v = (v >= 0.f) ? v : 0.2f * v;
        t[r][tx] = v;
    }
    __syncthreads();
    for (int r = ty; r < 32; r += 8)
        xout[b * 384 * NPTS + (o0 + r) * NPTS + n0 + tx] = t[tx][r];
}

// ---------------- final 384x384 GEMM -> d_out ----------------
__global__ __launch_bounds__(256) void gemm_last(const float* __restrict__ w,
                                                 float* __restrict__ out)
{
    int b  = blockIdx.x;
    int nt = blockIdx.y * 64;
    int ot = blockIdx.z * 64;

    __shared__ float xs[16][64];
    __shared__ float ws[16][65];

    int tid = threadIdx.x;
    int tx = tid & 15;  // n sub
    int ty = tid >> 4;  // o sub

    float acc[4][4];
#pragma unroll
    for (int a = 0; a < 4; a++)
#pragma unroll
        for (int c = 0; c < 4; c++) acc[a][c] = 0.f;

    const float* xb = g_xcon + (size_t)b * 384 * NPTS;
    for (int c0 = 0; c0 < 384; c0 += 16) {
        for (int e = tid; e < 1024; e += 256) {
            int kc = e >> 6, n = e & 63;
            xs[kc][n] = xb[(c0 + kc) * NPTS + nt + n];
        }
        for (int e = tid; e < 1024; e += 256) {
            int kc = e & 15, o = e >> 4;
            ws[kc][o] = w[(ot + o) * 384 + c0 + kc];
        }
        __syncthreads();
#pragma unroll
        for (int kc = 0; kc < 16; kc++) {
            float xv[4], wv[4];
#pragma unroll
            for (int in = 0; in < 4; in++) xv[in] = xs[kc][tx + 16*in];
#pragma unroll
            for (int io = 0; io < 4; io++) wv[io] = ws[kc][ty + 16*io];
#pragma unroll
            for (int io = 0; io < 4; io++)
#pragma unroll
                for (int in = 0; in < 4; in++)
                    acc[io][in] = fmaf(wv[io], xv[in], acc[io][in]);
        }
        __syncthreads();
    }
#pragma unroll
    for (int io = 0; io < 4; io++)
#pragma unroll
        for (int in = 0; in < 4; in++)
            out[(b * 384 + ot + ty + 16*io) * NPTS + nt + tx + 16*in] = acc[io][in];
}

extern "C" void kernel_launch(void* const* d_in, const int* in_sizes, int n_in,
                              void* d_out, int out_size)
{
    const float* x  = (const float*)d_in[0];
    const float* w[4]  = {(const float*)d_in[1], (const float*)d_in[4],
                          (const float*)d_in[7], (const float*)d_in[10]};
    const float* gm[4] = {(const float*)d_in[2], (const float*)d_in[5],
                          (const float*)d_in[8], (const float*)d_in[11]};
    const float* bt[4] = {(const float*)d_in[3], (const float*)d_in[6],
                          (const float*)d_in[9], (const float*)d_in[12]};
    const float* wl = (const float*)d_in[13];

    float* xcon = nullptr;
    cudaGetSymbolAddress((void**)&xcon, g_xcon);

    const int Cin[4]     = {256, 128, 128, 64};
    const int Oc[4]      = {128, 128, 64, 64};
    const int coffIn[4]  = {0, 0, 128, 256};
    const int coffOut[4] = {0, 128, 256, 320};

    for (int L = 0; L < 4; L++) {
        const float* xin;
        int bstride;
        if (L == 0) { xin = x;                        bstride = 256 * NPTS; }
        else        { xin = xcon + coffIn[L] * NPTS;  bstride = 384 * NPTS; }

        int gemm_ctas = BATCH * 16 * (Oc[L] / 64);
        fused_layer<<<KNN_CTAS + gemm_ctas, 256>>>(xin, w[L], Cin[L], Oc[L], bstride);
        gather_kernel<<<dim3(BATCH, NPTS / NT), Oc[L]>>>();
        stats_kernel<<<Oc[L], 64>>>(gm[L], bt[L]);
        act_transpose_kernel<<<dim3(BATCH, NPTS / 32, Oc[L] / 32), dim3(32, 8)>>>(
            xcon + coffOut[L] * NPTS);
    }
    gemm_last<<<dim3(BATCH, NPTS / 64, 384 / 64), 256>>>(wl, (float*)d_out);
}

// round 7
// speedup vs baseline: 1.0020x; 1.0002x over previous
#include <cuda_runtime.h>
#include <math.h>

#define BATCH 2
#define NPTS 1024
#define HEIGHT 32
#define CAND 224
#define KNN 64
#define NT 8
#define NCTA (BATCH*(NPTS/NT))
#define KNN_CTAS (BATCH*HEIGHT*4)   // 256: 4 CTAs per (b, 32-point block), 8 queries each

__device__ int   g_idx[BATCH*NPTS*KNN];
__device__ float g_Pt[BATCH*NPTS*128];
__device__ float g_Qt[BATCH*NPTS*128];
__device__ float g_R [BATCH*NPTS*128];
__device__ float g_part[NCTA*2*128];
__device__ float g_stat_a[128];
__device__ float g_stat_c[128];
__device__ float g_xcon[BATCH*384*NPTS];

// monotone float -> unsigned key (no NaNs present)
__device__ __forceinline__ unsigned key32(float f) {
    unsigned b = __float_as_uint(f);
    return b ^ ((b & 0x80000000u) ? 0xFFFFFFFFu : 0x80000000u);
}

// ============ fused: KNN (256 CTAs) || gemm P/Q (rest) ============
__global__ __launch_bounds__(256) void fused_layer(const float* __restrict__ x,
                                                   const float* __restrict__ w,
                                                   int C, int Oc, int bstride)
{
    __shared__ union {
        float cs[8 * CAND];                               // knn candidate tile
        struct { float xs[16*64], w1s[16*65], wds[16*65]; } g;  // gemm tiles
    } sm;

    int bx  = blockIdx.x;
    int tid = threadIdx.x;

    if (bx < KNN_CTAS) {
        // ---------------- KNN: warp-per-query ----------------
        int b   = bx >> 7;
        int rem = bx & 127;
        int i   = rem >> 2;          // 32-point block row
        int sub = rem & 3;           // which 8 queries
        const float* xb = x + (size_t)b * bstride;
        int start = (i - 3) * 32;

        int lane = tid & 31;
        int wq   = tid >> 5;         // warp id 0..7
        int q    = sub * 8 + wq;     // query within block row (0..31)

        float acc[7];
#pragma unroll
        for (int u = 0; u < 7; u++) acc[u] = 0.f;

        for (int c0 = 0; c0 < C; c0 += 8) {
            for (int e = tid; e < 8 * CAND; e += 256) {
                int cc = e / CAND, p = e - cc * CAND;
                int j = start + p;
                sm.cs[cc * CAND + p] = (j >= 0 && j < NPTS) ? xb[(c0 + cc) * NPTS + j] : 0.f;
            }
            __syncthreads();
#pragma unroll
            for (int cc = 0; cc < 8; cc++) {
                float qv = sm.cs[cc * CAND + 96 + q];     // query = candidate slot 96+q
#pragma unroll
                for (int u = 0; u < 7; u++) {
                    float d = qv - sm.cs[cc * CAND + lane + 32 * u];
                    acc[u] = fmaf(d, d, acc[u]);
                }
            }
            __syncthreads();
        }

        // keys in registers; invalid candidates -> 0 sentinel
        unsigned long long pv[7];
#pragma unroll
        for (int u = 0; u < 7; u++) {
            int p = lane + 32 * u;
            int j = start + p;
            pv[u] = (j >= 0 && j < NPTS)
                    ? (((unsigned long long)key32(-acc[u]) << 32) | (unsigned)(~p))
                    : 0ull;
        }

        int n = i * 32 + q;
        int pick0 = 0, pick1 = 0;
        for (int k = 0; k < KNN; k++) {
            unsigned long long best = pv[0];
#pragma unroll
            for (int u = 1; u < 7; u++) if (pv[u] > best) best = pv[u];
#pragma unroll
            for (int s = 16; s > 0; s >>= 1) {
                unsigned long long o2 = __shfl_xor_sync(0xffffffffu, best, s);
                if (o2 > best) best = o2;
            }
            unsigned pos = ~(unsigned)best;
            if ((int)(pos & 31) == lane) {
                int slot = pos >> 5;
#pragma unroll
                for (int u = 0; u < 7; u++)
                    if (u == slot) pv[u] = 0ull;
            }
            if (k < 32) { if (lane == k)      pick0 = start + (int)pos; }
            else        { if (lane == k - 32) pick1 = start + (int)pos; }
        }
        g_idx[(b * NPTS + n) * KNN + lane]      = pick0;
        g_idx[(b * NPTS + n) * KNN + 32 + lane] = pick1;
    } else {
        // ------------- P = W1@x, Q = (W2-W1)@x, stored [b][n][o] -------------
        int gid  = bx - KNN_CTAS;
        int zcnt = Oc >> 6;
        int gz   = gid % zcnt;
        int rest = gid / zcnt;
        int gy   = rest & 15;
        int b    = rest >> 4;

        int nt = gy * 64;
        int ot = gz * 64;
        int tx = tid & 15;   // o sub
        int ty = tid >> 4;   // n sub

        float accP[4][4], accQ[4][4];
#pragma unroll
        for (int a = 0; a < 4; a++)
#pragma unroll
            for (int c = 0; c < 4; c++) { accP[a][c] = 0.f; accQ[a][c] = 0.f; }

        const float* xb = x + (size_t)b * bstride;
        int twoC = 2 * C;

        for (int c0 = 0; c0 < C; c0 += 16) {
            for (int e = tid; e < 1024; e += 256) {
                int kc = e >> 6, nn = e & 63;
                sm.g.xs[kc * 64 + nn] = xb[(c0 + kc) * NPTS + nt + nn];
            }
            for (int e = tid; e < 1024; e += 256) {
                int kc = e & 15, o = e >> 4;
                const float* wr = w + (ot + o) * twoC + c0 + kc;
                float w1 = wr[0];
                float w2 = wr[C];
                sm.g.w1s[kc * 65 + o] = w1;
                sm.g.wds[kc * 65 + o] = w2 - w1;
            }
            __syncthreads();
#pragma unroll
            for (int kc = 0; kc < 16; kc++) {
                float a1[4], ad[4], xv[4];
#pragma unroll
                for (int io = 0; io < 4; io++) { a1[io] = sm.g.w1s[kc*65 + tx + 16*io];
                                                 ad[io] = sm.g.wds[kc*65 + tx + 16*io]; }
#pragma unroll
                for (int in = 0; in < 4; in++) xv[in] = sm.g.xs[kc*64 + ty + 16*in];
#pragma unroll
                for (int io = 0; io < 4; io++)
#pragma unroll
                    for (int in = 0; in < 4; in++) {
                        accP[io][in] = fmaf(a1[io], xv[in], accP[io][in]);
                        accQ[io][in] = fmaf(ad[io], xv[in], accQ[io][in]);
                    }
            }
            __syncthreads();
        }
#pragma unroll
        for (int io = 0; io < 4; io++)
#pragma unroll
            for (int in = 0; in < 4; in++) {
                int o = ot + tx + 16*io;
                int nn = nt + ty + 16*in;
                g_Pt[(b*NPTS + nn)*128 + o] = accP[io][in];
                g_Qt[(b*NPTS + nn)*128 + o] = accQ[io][in];
            }
    }
}

// ---- gather: per (n,o): v_k = P[j_k,o] + Q[n,o]; max, sum, sumsq ----
__global__ void gather_kernel()
{
    int b   = blockIdx.x;
    int n0  = blockIdx.y * NT;
    int O   = blockDim.x;
    int o   = threadIdx.x;

    __shared__ int idxs[NT * KNN];
    for (int e = o; e < NT * KNN; e += O)
        idxs[e] = g_idx[(b * NPTS + n0) * KNN + e];
    __syncthreads();

    float s1a = 0.f, s2a = 0.f;
    for (int t = 0; t < NT; t++) {
        int n = n0 + t;
        float qv = g_Qt[(b * NPTS + n) * 128 + o];
        float m = -3e38f, s1 = 0.f, s2 = 0.f;
#pragma unroll 8
        for (int k = 0; k < KNN; k++) {
            float v = g_Pt[(b * NPTS + idxs[t * KNN + k]) * 128 + o] + qv;
            m = fmaxf(m, v);
            s1 += v;
            s2 = fmaf(v, v, s2);
        }
        g_R[(b * NPTS + n) * 128 + o] = m;
        s1a += s1;
        s2a += s2;
    }
    int cta = b * (NPTS / NT) + blockIdx.y;
    g_part[(cta * 2 + 0) * 128 + o] = s1a;
    g_part[(cta * 2 + 1) * 128 + o] = s2a;
}

// --------- per-channel BN coefficients: one CTA per channel ---------
__global__ void stats_kernel(const float* __restrict__ gm, const float* __restrict__ bt)
{
    int o = blockIdx.x;
    int t = threadIdx.x;   // 64 threads
    double s1 = 0.0, s2 = 0.0;
    for (int c = t; c < NCTA; c += 64) {
        s1 += (double)g_part[(c * 2 + 0) * 128 + o];
        s2 += (double)g_part[(c * 2 + 1) * 128 + o];
    }
    __shared__ double sh1[64], sh2[64];
    sh1[t] = s1; sh2[t] = s2;
    __syncthreads();
#pragma unroll
    for (int s = 32; s > 0; s >>= 1) {
        if (t < s) { sh1[t] += sh1[t + s]; sh2[t] += sh2[t + s]; }
        __syncthreads();
    }
    if (t == 0) {
        double cnt = (double)BATCH * NPTS * KNN;
        double mu  = sh1[0] / cnt;
        double var = sh2[0] / cnt - mu * mu;
        float a = gm[o] / (float)sqrt(var + 1e-5);
        g_stat_a[o] = a;
        g_stat_c[o] = bt[o] - (float)mu * a;
    }
}

// ---- affine-BN + leaky-relu + transpose [b][n][o] -> [b][o][n] ----
__global__ void act_transpose_kernel(float* __restrict__ xout)
{
    __shared__ float t[32][33];
    int b  = blockIdx.x;
    int n0 = blockIdx.y * 32;
    int o0 = blockIdx.z * 32;
    int tx = threadIdx.x, ty = threadIdx.y;
    float a = g_stat_a[o0 + tx];
    float c = g_stat_c[o0 + tx];
    for (int r = ty; r < 32; r += 8) {
        float v = g_R[(b * NPTS + n0 + r) * 128 + o0 + tx];
        v = a * v + c;
        v = (v >= 0.f) ? v : 0.2f * v;
        t[r][tx] = v;
    }
    __syncthreads();
    for (int r = ty; r < 32; r += 8)
        xout[b * 384 * NPTS + (o0 + r) * NPTS + n0 + tx] = t[tx][r];
}

// ---------------- final 384x384 GEMM -> d_out ----------------
__global__ __launch_bounds__(256) void gemm_last(const float* __restrict__ w,
                                                 float* __restrict__ out)
{
    int b  = blockIdx.x;
    int nt = blockIdx.y * 64;
    int ot = blockIdx.z * 64;

    __shared__ float xs[16][64];
    __shared__ float ws[16][65];

    int tid = threadIdx.x;
    int tx = tid & 15;  // n sub
    int ty = tid >> 4;  // o sub

    float acc[4][4];
#pragma unroll
    for (int a = 0; a < 4; a++)
#pragma unroll
        for (int c = 0; c < 4; c++) acc[a][c] = 0.f;

    const float* xb = g_xcon + (size_t)b * 384 * NPTS;
    for (int c0 = 0; c0 < 384; c0 += 16) {
        for (int e = tid; e < 1024; e += 256) {
            int kc = e >> 6, n = e & 63;
            xs[kc][n] = xb[(c0 + kc) * NPTS + nt + n];
        }
        for (int e = tid; e < 1024; e += 256) {
            int kc = e & 15, o = e >> 4;
            ws[kc][o] = w[(ot + o) * 384 + c0 + kc];
        }
        __syncthreads();
#pragma unroll
        for (int kc = 0; kc < 16; kc++) {
            float xv[4], wv[4];
#pragma unroll
            for (int in = 0; in < 4; in++) xv[in] = xs[kc][tx + 16*in];
#pragma unroll
            for (int io = 0; io < 4; io++) wv[io] = ws[kc][ty + 16*io];
#pragma unroll
            for (int io = 0; io < 4; io++)
#pragma unroll
                for (int in = 0; in < 4; in++)
                    acc[io][in] = fmaf(wv[io], xv[in], acc[io][in]);
        }
        __syncthreads();
    }
#pragma unroll
    for (int io = 0; io < 4; io++)
#pragma unroll
        for (int in = 0; in < 4; in++)
            out[(b * 384 + ot + ty + 16*io) * NPTS + nt + tx + 16*in] = acc[io][in];
}

extern "C" void kernel_launch(void* const* d_in, const int* in_sizes, int n_in,
                              void* d_out, int out_size)
{
    const float* x  = (const float*)d_in[0];
    const float* w[4]  = {(const float*)d_in[1], (const float*)d_in[4],
                          (const float*)d_in[7], (const float*)d_in[10]};
    const float* gm[4] = {(const float*)d_in[2], (const float*)d_in[5],
                          (const float*)d_in[8], (const float*)d_in[11]};
    const float* bt[4] = {(const float*)d_in[3], (const float*)d_in[6],
                          (const float*)d_in[9], (const float*)d_in[12]};
    const float* wl = (const float*)d_in[13];

    float* xcon = nullptr;
    cudaGetSymbolAddress((void**)&xcon, g_xcon);

    const int Cin[4]     = {256, 128, 128, 64};
    const int Oc[4]      = {128, 128, 64, 64};
    const int coffIn[4]  = {0, 0, 128, 256};
    const int coffOut[4] = {0, 128, 256, 320};

    for (int L = 0; L < 4; L++) {
        const float* xin;
        int bstride;
        if (L == 0) { xin = x;                        bstride = 256 * NPTS; }
        else        { xin = xcon + coffIn[L] * NPTS;  bstride = 384 * NPTS; }

        int gemm_ctas = BATCH * 16 * (Oc[L] / 64);
        fused_layer<<<KNN_CTAS + gemm_ctas, 256>>>(xin, w[L], Cin[L], Oc[L], bstride);
        gather_kernel<<<dim3(BATCH, NPTS / NT), Oc[L]>>>();
        stats_kernel<<<Oc[L], 64>>>(gm[L], bt[L]);
        act_transpose_kernel<<<dim3(BATCH, NPTS / 32, Oc[L] / 32), dim3(32, 8)>>>(
            xcon + coffOut[L] * NPTS);
    }
    gemm_last<<<dim3(BATCH, NPTS / 64, 384 / 64), 256>>>(wl, (float*)d_out);
}

// round 8
// speedup vs baseline: 1.0058x; 1.0038x over previous
#include <cuda_runtime.h>
#include <math.h>

#define BATCH 2
#define NPTS 1024
#define HEIGHT 32
#define CAND 224
#define KNN 64
#define NT 8
#define NCTA (BATCH*(NPTS/NT))
#define KNN_CTAS (BATCH*HEIGHT*4)   // 256: 4 CTAs per (b, 32-point block), 8 queries each

__device__ int   g_idx[BATCH*NPTS*KNN];
__device__ float g_Pt[BATCH*NPTS*128];
__device__ float g_Qt[BATCH*NPTS*128];
__device__ float g_R [BATCH*NPTS*128];
__device__ float g_part[NCTA*2*128];
__device__ float g_stat_a[128];
__device__ float g_stat_c[128];
__device__ float g_xcon[BATCH*384*NPTS];

// monotone float -> unsigned key (no NaNs present)
__device__ __forceinline__ unsigned key32(float f) {
    unsigned b = __float_as_uint(f);
    return b ^ ((b & 0x80000000u) ? 0xFFFFFFFFu : 0x80000000u);
}

// ============ fused: KNN (256 CTAs) || gemm P/Q (rest) ============
__global__ __launch_bounds__(256) void fused_layer(const float* __restrict__ x,
                                                   const float* __restrict__ w,
                                                   int C, int Oc, int bstride)
{
    __shared__ union {
        float cs[8 * CAND];                               // knn candidate tile
        struct { float xs[16*64], w1s[16*65], wds[16*65]; } g;  // gemm tiles
    } sm;

    int bx  = blockIdx.x;
    int tid = threadIdx.x;

    if (bx < KNN_CTAS) {
        // ---------------- KNN: warp-per-query ----------------
        int b   = bx >> 7;
        int rem = bx & 127;
        int i   = rem >> 2;          // 32-point block row
        int sub = rem & 3;           // which 8 queries
        const float* xb = x + (size_t)b * bstride;
        int start = (i - 3) * 32;

        int lane = tid & 31;
        int wq   = tid >> 5;         // warp id 0..7
        int q    = sub * 8 + wq;     // query within block row (0..31)

        float acc[7];
#pragma unroll
        for (int u = 0; u < 7; u++) acc[u] = 0.f;

        for (int c0 = 0; c0 < C; c0 += 8) {
            for (int e = tid; e < 8 * CAND; e += 256) {
                int cc = e / CAND, p = e - cc * CAND;
                int j = start + p;
                sm.cs[cc * CAND + p] = (j >= 0 && j < NPTS) ? xb[(c0 + cc) * NPTS + j] : 0.f;
            }
            __syncthreads();
#pragma unroll
            for (int cc = 0; cc < 8; cc++) {
                float qv = sm.cs[cc * CAND + 96 + q];     // query = candidate slot 96+q
#pragma unroll
                for (int u = 0; u < 7; u++) {
                    float d = qv - sm.cs[cc * CAND + lane + 32 * u];
                    acc[u] = fmaf(d, d, acc[u]);
                }
            }
            __syncthreads();
        }

        // keys in registers; invalid candidates -> 0 sentinel
        unsigned long long pv[7];
#pragma unroll
        for (int u = 0; u < 7; u++) {
            int p = lane + 32 * u;
            int j = start + p;
            pv[u] = (j >= 0 && j < NPTS)
                    ? (((unsigned long long)key32(-acc[u]) << 32) | (unsigned)(~p))
                    : 0ull;
        }

        int n = i * 32 + q;
        int pick0 = 0, pick1 = 0;
        for (int k = 0; k < KNN; k++) {
            unsigned long long best = pv[0];
#pragma unroll
            for (int u = 1; u < 7; u++) if (pv[u] > best) best = pv[u];
#pragma unroll
            for (int s = 16; s > 0; s >>= 1) {
                unsigned long long o2 = __shfl_xor_sync(0xffffffffu, best, s);
                if (o2 > best) best = o2;
            }
            unsigned pos = ~(unsigned)best;
            if ((int)(pos & 31) == lane) {
                int slot = pos >> 5;
#pragma unroll
                for (int u = 0; u < 7; u++)
                    if (u == slot) pv[u] = 0ull;
            }
            if (k < 32) { if (lane == k)      pick0 = start + (int)pos; }
            else        { if (lane == k - 32) pick1 = start + (int)pos; }
        }
        g_idx[(b * NPTS + n) * KNN + lane]      = pick0;
        g_idx[(b * NPTS + n) * KNN + 32 + lane] = pick1;
    } else {
        // ------------- P = W1@x, Q = (W2-W1)@x, stored [b][n][o] -------------
        int gid  = bx - KNN_CTAS;
        int zcnt = Oc >> 6;
        int gz   = gid % zcnt;
        int rest = gid / zcnt;
        int gy   = rest & 15;
        int b    = rest >> 4;

        int nt = gy * 64;
        int ot = gz * 64;
        int tx = tid & 15;   // o sub
        int ty = tid >> 4;   // n sub

        float accP[4][4], accQ[4][4];
#pragma unroll
        for (int a = 0; a < 4; a++)
#pragma unroll
            for (int c = 0; c < 4; c++) { accP[a][c] = 0.f; accQ[a][c] = 0.f; }

        const float* xb = x + (size_t)b * bstride;
        int twoC = 2 * C;

        for (int c0 = 0; c0 < C; c0 += 16) {
            for (int e = tid; e < 1024; e += 256) {
                int kc = e >> 6, nn = e & 63;
                sm.g.xs[kc * 64 + nn] = xb[(c0 + kc) * NPTS + nt + nn];
            }
            for (int e = tid; e < 1024; e += 256) {
                int kc = e & 15, o = e >> 4;
                const float* wr = w + (ot + o) * twoC + c0 + kc;
                float w1 = wr[0];
                float w2 = wr[C];
                sm.g.w1s[kc * 65 + o] = w1;
                sm.g.wds[kc * 65 + o] = w2 - w1;
            }
            __syncthreads();
#pragma unroll
            for (int kc = 0; kc < 16; kc++) {
                float a1[4], ad[4], xv[4];
#pragma unroll
                for (int io = 0; io < 4; io++) { a1[io] = sm.g.w1s[kc*65 + tx + 16*io];
                                                 ad[io] = sm.g.wds[kc*65 + tx + 16*io]; }
#pragma unroll
                for (int in = 0; in < 4; in++) xv[in] = sm.g.xs[kc*64 + ty + 16*in];
#pragma unroll
                for (int io = 0; io < 4; io++)
#pragma unroll
                    for (int in = 0; in < 4; in++) {
                        accP[io][in] = fmaf(a1[io], xv[in], accP[io][in]);
                        accQ[io][in] = fmaf(ad[io], xv[in], accQ[io][in]);
                    }
            }
            __syncthreads();
        }
#pragma unroll
        for (int io = 0; io < 4; io++)
#pragma unroll
            for (int in = 0; in < 4; in++) {
                int o = ot + tx + 16*io;
                int nn = nt + ty + 16*in;
                g_Pt[(b*NPTS + nn)*128 + o] = accP[io][in];
                g_Qt[(b*NPTS + nn)*128 + o] = accQ[io][in];
            }
    }
}

// ---- gather: per (n,o): v_k = P[j_k,o] + Q[n,o]; max, sum, sumsq ----
__global__ void gather_kernel()
{
    int b   = blockIdx.x;
    int n0  = blockIdx.y * NT;
    int O   = blockDim.x;
    int o   = threadIdx.x;

    __shared__ int idxs[NT * KNN];
    for (int e = o; e < NT * KNN; e += O)
        idxs[e] = g_idx[(b * NPTS + n0) * KNN + e];
    __syncthreads();

    float s1a = 0.f, s2a = 0.f;
    for (int t = 0; t < NT; t++) {
        int n = n0 + t;
        float qv = g_Qt[(b * NPTS + n) * 128 + o];
        float m = -3e38f, s1 = 0.f, s2 = 0.f;
#pragma unroll 8
        for (int k = 0; k < KNN; k++) {
            float v = g_Pt[(b * NPTS + idxs[t * KNN + k]) * 128 + o] + qv;
            m = fmaxf(m, v);
            s1 += v;
            s2 = fmaf(v, v, s2);
        }
        g_R[(b * NPTS + n) * 128 + o] = m;
        s1a += s1;
        s2a += s2;
    }
    int cta = b * (NPTS / NT) + blockIdx.y;
    g_part[(cta * 2 + 0) * 128 + o] = s1a;
    g_part[(cta * 2 + 1) * 128 + o] = s2a;
}

// --------- per-channel BN coefficients: one CTA per channel ---------
__global__ void stats_kernel(const float* __restrict__ gm, const float* __restrict__ bt)
{
    int o = blockIdx.x;
    int t = threadIdx.x;   // 64 threads
    double s1 = 0.0, s2 = 0.0;
    for (int c = t; c < NCTA; c += 64) {
        s1 += (double)g_part[(c * 2 + 0) * 128 + o];
        s2 += (double)g_part[(c * 2 + 1) * 128 + o];
    }
    __shared__ double sh1[64], sh2[64];
    sh1[t] = s1; sh2[t] = s2;
    __syncthreads();
#pragma unroll
    for (int s = 32; s > 0; s >>= 1) {
        if (t < s) { sh1[t] += sh1[t + s]; sh2[t] += sh2[t + s]; }
        __syncthreads();
    }
    if (t == 0) {
        double cnt = (double)BATCH * NPTS * KNN;
        double mu  = sh1[0] / cnt;
        double var = sh2[0] / cnt - mu * mu;
        float a = gm[o] / (float)sqrt(var + 1e-5);
        g_stat_a[o] = a;
        g_stat_c[o] = bt[o] - (float)mu * a;
    }
}

// ---- affine-BN + leaky-relu + transpose [b][n][o] -> [b][o][n] ----
__global__ void act_transpose_kernel(float* __restrict__ xout)
{
    __shared__ float t[32][33];
    int b  = blockIdx.x;
    int n0 = blockIdx.y * 32;
    int o0 = blockIdx.z * 32;
    int tx = threadIdx.x, ty = threadIdx.y;
    float a = g_stat_a[o0 + tx];
    float c = g_stat_c[o0 + tx];
    for (int r = ty; r < 32; r += 8) {
        float v = g_R[(b * NPTS + n0 + r) * 128 + o0 + tx];
        v = a * v + c;
        v = (v >= 0.f) ? v : 0.2f * v;
        t[r][tx] = v;
    }
    __syncthreads();
    for (int r = ty; r < 32; r += 8)
        xout[b * 384 * NPTS + (o0 + r) * NPTS + n0 + tx] = t[tx][r];
}

// ---------------- final 384x384 GEMM -> d_out ----------------
__global__ __launch_bounds__(256) void gemm_last(const float* __restrict__ w,
                                                 float* __restrict__ out)
{
    int b  = blockIdx.x;
    int nt = blockIdx.y * 64;
    int ot = blockIdx.z * 64;

    __shared__ float xs[16][64];
    __shared__ float ws[16][65];

    int tid = threadIdx.x;
    int tx = tid & 15;  // n sub
    int ty = tid >> 4;  // o sub

    float acc[4][4];
#pragma unroll
    for (int a = 0; a < 4; a++)
#pragma unroll
        for (int c = 0; c < 4; c++) acc[a][c] = 0.f;

    const float* xb = g_xcon + (size_t)b * 384 * NPTS;
    for (int c0 = 0; c0 < 384; c0 += 16) {
        for (int e = tid; e < 1024; e += 256) {
            int kc = e >> 6, n = e & 63;
            xs[kc][n] = xb[(c0 + kc) * NPTS + nt + n];
        }
        for (int e = tid; e < 1024; e += 256) {
            int kc = e & 15, o = e >> 4;
            ws[kc][o] = w[(ot + o) * 384 + c0 + kc];
        }
        __syncthreads();
#pragma unroll
        for (int kc = 0; kc < 16; kc++) {
            float xv[4], wv[4];
#pragma unroll
            for (int in = 0; in < 4; in++) xv[in] = xs[kc][tx + 16*in];
#pragma unroll
            for (int io = 0; io < 4; io++) wv[io] = ws[kc][ty + 16*io];
#pragma unroll
            for (int io = 0; io < 4; io++)
#pragma unroll
                for (int in = 0; in < 4; in++)
                    acc[io][in] = fmaf(wv[io], xv[in], acc[io][in]);
        }
        __syncthreads();
    }
#pragma unroll
    for (int io = 0; io < 4; io++)
#pragma unroll
        for (int in = 0; in < 4; in++)
            out[(b * 384 + ot + ty + 16*io) * NPTS + nt + tx + 16*in] = acc[io][in];
}

extern "C" void kernel_launch(void* const* d_in, const int* in_sizes, int n_in,
                              void* d_out, int out_size)
{
    const float* x  = (const float*)d_in[0];
    const float* w[4]  = {(const float*)d_in[1], (const float*)d_in[4],
                          (const float*)d_in[7], (const float*)d_in[10]};
    const float* gm[4] = {(const float*)d_in[2], (const float*)d_in[5],
                          (const float*)d_in[8], (const float*)d_in[11]};
    const float* bt[4] = {(const float*)d_in[3], (const float*)d_in[6],
                          (const float*)d_in[9], (const float*)d_in[12]};
    const float* wl = (const float*)d_in[13];

    float* xcon = nullptr;
    cudaGetSymbolAddress((void**)&xcon, g_xcon);

    const int Cin[4]     = {256, 128, 128, 64};
    const int Oc[4]      = {128, 128, 64, 64};
    const int coffIn[4]  = {0, 0, 128, 256};
    const int coffOut[4] = {0, 128, 256, 320};

    for (int L = 0; L < 4; L++) {
        const float* xin;
        int bstride;
        if (L == 0) { xin = x;                        bstride = 256 * NPTS; }
        else        { xin = xcon + coffIn[L] * NPTS;  bstride = 384 * NPTS; }

        int gemm_ctas = BATCH * 16 * (Oc[L] / 64);
        fused_layer<<<KNN_CTAS + gemm_ctas, 256>>>(xin, w[L], Cin[L], Oc[L], bstride);
        gather_kernel<<<dim3(BATCH, NPTS / NT), Oc[L]>>>();
        stats_kernel<<<Oc[L], 64>>>(gm[L], bt[L]);
        act_transpose_kernel<<<dim3(BATCH, NPTS / 32, Oc[L] / 32), dim3(32, 8)>>>(
            xcon + coffOut[L] * NPTS);
    }
    gemm_last<<<dim3(BATCH, NPTS / 64, 384 / 64), 256>>>(wl, (float*)d_out);
}